// round 16
// baseline (speedup 1.0000x reference)
#include <cuda_runtime.h>
#include <cstdint>

constexpr int Bsz  = 8;
constexpr int Cdim = 512;
constexpr int Ldim = 8192;
constexpr int Hn   = 8;
constexpr int Dh   = 64;
constexpr int KSPLIT = 8;   // gram split-K slabs

// ---------------- scratch (static device arrays; never passed as kernel args) --
__device__ float g_Gpart[(size_t)KSPLIT * Bsz * Cdim * Cdim];   // 64 MB
__device__ float g_G[(size_t)Bsz * Cdim * Cdim];
__device__ float g_kvpart[8ull * Bsz * Hn * Dh * Dh];
__device__ float g_W2[(size_t)Bsz * Cdim * Cdim];
__device__ float g_W3[(size_t)Bsz * Cdim * Cdim];

// packed dual-FMA helpers (base PTX, sm_100+)
static __device__ __forceinline__ unsigned long long dup2(float a) {
    unsigned long long r;
    asm("mov.b64 %0, {%1, %1};" : "=l"(r) : "f"(a));
    return r;
}
static __device__ __forceinline__ void fma2(unsigned long long& c,
                                            unsigned long long a,
                                            unsigned long long b) {
    asm("fma.rn.f32x2 %0, %1, %2, %0;" : "+l"(c) : "l"(a), "l"(b));
}
static __device__ __forceinline__ float lo32(unsigned long long v) {
    return __uint_as_float((unsigned)(v & 0xFFFFFFFFull));
}
static __device__ __forceinline__ float hi32(unsigned long long v) {
    return __uint_as_float((unsigned)(v >> 32));
}

// ---------------------------------------------------------------------------
// Kernel 1: Gram partials; f32x2 with PRE-DUPLICATED A in smem (broadcast
// reads => zero extra crossbar cost, kills the 8 dup movs per kk).
// G[b] = Xg[b] @ Xg[b]^T, 10 symmetric tile pairs, split-K=8 slabs.
// ---------------------------------------------------------------------------
__global__ __launch_bounds__(256, 2) void gram_kernel(const float* __restrict__ Xg) {
    const int pair = blockIdx.x, ks = blockIdx.y, b = blockIdx.z;
    int ti = 0, t = pair;
    while (t >= 4 - ti) { t -= 4 - ti; ti++; }
    const int tj = ti + t;

    const float* X   = Xg + (size_t)b * Cdim * Ldim;
    const float* Ag0 = X + (size_t)ti * 128 * Ldim;
    const float* Bg0 = X + (size_t)tj * 128 * Ldim;
    const int k0 = ks * 1024;

    __shared__ float Ad[16][272];   // [k][2m] duplicated A pairs (+pad)
    __shared__ float Bs[16][132];   // [k][n]

    const int tid = threadIdx.x;
    const int tx = tid & 15, ty = tid >> 4;
    const int lrow = tid >> 2, lc4 = tid & 3;

    unsigned long long acc[8][4];
#pragma unroll
    for (int i = 0; i < 8; i++)
#pragma unroll
        for (int j = 0; j < 4; j++) acc[i][j] = 0ull;

    const float* ApA = Ag0 + (size_t)lrow * Ldim + lc4 * 4 + k0;
    const float* ApB = Ag0 + (size_t)(lrow + 64) * Ldim + lc4 * 4 + k0;
    const float* BpA = Bg0 + (size_t)lrow * Ldim + lc4 * 4 + k0;
    const float* BpB = Bg0 + (size_t)(lrow + 64) * Ldim + lc4 * 4 + k0;

    float4 a0 = *(const float4*)(ApA);
    float4 a1 = *(const float4*)(ApB);
    float4 b0 = *(const float4*)(BpA);
    float4 b1 = *(const float4*)(BpB);

    for (int kt = 0; kt < 1024; kt += 16) {
        __syncthreads();   // previous compute done before smem overwrite
        *(unsigned long long*)&Ad[lc4*4+0][2*lrow]       = dup2(a0.x);
        *(unsigned long long*)&Ad[lc4*4+1][2*lrow]       = dup2(a0.y);
        *(unsigned long long*)&Ad[lc4*4+2][2*lrow]       = dup2(a0.z);
        *(unsigned long long*)&Ad[lc4*4+3][2*lrow]       = dup2(a0.w);
        *(unsigned long long*)&Ad[lc4*4+0][2*lrow + 128] = dup2(a1.x);
        *(unsigned long long*)&Ad[lc4*4+1][2*lrow + 128] = dup2(a1.y);
        *(unsigned long long*)&Ad[lc4*4+2][2*lrow + 128] = dup2(a1.z);
        *(unsigned long long*)&Ad[lc4*4+3][2*lrow + 128] = dup2(a1.w);
        Bs[lc4*4+0][lrow]    = b0.x; Bs[lc4*4+1][lrow]    = b0.y;
        Bs[lc4*4+2][lrow]    = b0.z; Bs[lc4*4+3][lrow]    = b0.w;
        Bs[lc4*4+0][lrow+64] = b1.x; Bs[lc4*4+1][lrow+64] = b1.y;
        Bs[lc4*4+2][lrow+64] = b1.z; Bs[lc4*4+3][lrow+64] = b1.w;
        __syncthreads();
        if (kt + 16 < 1024) {   // prefetch next stage under the compute
            a0 = *(const float4*)(ApA + kt + 16);
            a1 = *(const float4*)(ApB + kt + 16);
            b0 = *(const float4*)(BpA + kt + 16);
            b1 = *(const float4*)(BpB + kt + 16);
        }
#pragma unroll
        for (int kk = 0; kk < 16; kk++) {
            float4 aq0 = *(const float4*)&Ad[kk][8*ty];         // m pairs 0,1
            float4 aq1 = *(const float4*)&Ad[kk][8*ty + 4];     // m pairs 2,3
            float4 aq2 = *(const float4*)&Ad[kk][8*ty + 128];   // m pairs 4,5
            float4 aq3 = *(const float4*)&Ad[kk][8*ty + 132];   // m pairs 6,7
            unsigned long long ap[8];
            ap[0] = *(unsigned long long*)&aq0.x; ap[1] = *(unsigned long long*)&aq0.z;
            ap[2] = *(unsigned long long*)&aq1.x; ap[3] = *(unsigned long long*)&aq1.z;
            ap[4] = *(unsigned long long*)&aq2.x; ap[5] = *(unsigned long long*)&aq2.z;
            ap[6] = *(unsigned long long*)&aq3.x; ap[7] = *(unsigned long long*)&aq3.z;
            float4 bq0 = *(const float4*)&Bs[kk][tx*4];
            float4 bq1 = *(const float4*)&Bs[kk][64 + tx*4];
            unsigned long long bp[4];
            bp[0] = *(unsigned long long*)&bq0.x;
            bp[1] = *(unsigned long long*)&bq0.z;
            bp[2] = *(unsigned long long*)&bq1.x;
            bp[3] = *(unsigned long long*)&bq1.z;
#pragma unroll
            for (int i = 0; i < 8; i++)
#pragma unroll
                for (int j = 0; j < 4; j++) fma2(acc[i][j], ap[i], bp[j]);
        }
    }

    float* Gp = g_Gpart + ((size_t)ks * Bsz + b) * Cdim * Cdim;
#pragma unroll
    for (int i = 0; i < 8; i++) {
        const int m = ti * 128 + ((i < 4) ? (ty*4 + i) : (64 + ty*4 + i - 4));
        float av[8];
#pragma unroll
        for (int j = 0; j < 4; j++) { av[2*j] = lo32(acc[i][j]); av[2*j+1] = hi32(acc[i][j]); }
#pragma unroll
        for (int j = 0; j < 8; j++) {
            const int n = tj * 128 + ((j < 4) ? (tx*4 + j) : (64 + tx*4 + j - 4));
            Gp[(size_t)m * Cdim + n] = av[j];
            if (ti != tj) Gp[(size_t)n * Cdim + m] = av[j];
        }
    }
}

// Kernel 2: reduce the 8 split-K slabs (deterministic).
__global__ void greduce_kernel() {
    const size_t n   = (size_t)Bsz * Cdim * Cdim;
    const size_t idx = (size_t)blockIdx.x * blockDim.x + threadIdx.x;
    if (idx < n) {
        float s = 0.f;
#pragma unroll
        for (int t = 0; t < KSPLIT; t++) s += g_Gpart[(size_t)t * n + idx];
        g_G[idx] = s;
    }
}

// ---------------------------------------------------------------------------
// Kernel 3: kv partials (fp32, proven): kv[b,h] = Wk_h @ G[b] @ Wv_h^T
// ---------------------------------------------------------------------------
__global__ __launch_bounds__(256) void kv_kernel(const float* __restrict__ Wk,
                                                 const float* __restrict__ Wv) {
    const int ct = blockIdx.x;
    const int h  = blockIdx.y;
    const int b  = blockIdx.z;
    const float* G = g_G + (size_t)b * Cdim * Cdim;
    const int c0 = ct * 64;

    __shared__ float Wks[16][68];
    __shared__ float Gs[16][68];
    __shared__ float Ts[64][68];
    __shared__ float Wvs[64][68];

    const int tid = threadIdx.x;
    const int tx = tid & 15, ty = tid >> 4;

    float acc[4][4];
#pragma unroll
    for (int i = 0; i < 4; i++)
#pragma unroll
        for (int j = 0; j < 4; j++) acc[i][j] = 0.f;

    for (int k = 0; k < 512; k += 16) {
        const int row = tid >> 2, c4 = tid & 3;
        float4 w4 = *(const float4*)(Wk + (size_t)(h*64 + row) * Cdim + k + c4*4);
        const int kr = tid >> 4, f4 = tid & 15;
        float4 g4 = *(const float4*)(G + (size_t)(k + kr) * Cdim + c0 + f4*4);
        __syncthreads();
        Wks[c4*4+0][row] = w4.x; Wks[c4*4+1][row] = w4.y;
        Wks[c4*4+2][row] = w4.z; Wks[c4*4+3][row] = w4.w;
        *(float4*)&Gs[kr][f4*4] = g4;
        __syncthreads();
#pragma unroll
        for (int kk = 0; kk < 16; kk++) {
            float a4[4], b4[4];
            *(float4*)&a4[0] = *(const float4*)&Wks[kk][ty*4];
            *(float4*)&b4[0] = *(const float4*)&Gs[kk][tx*4];
#pragma unroll
            for (int i = 0; i < 4; i++)
#pragma unroll
                for (int j = 0; j < 4; j++) acc[i][j] += a4[i] * b4[j];
        }
    }
#pragma unroll
    for (int i = 0; i < 4; i++)
#pragma unroll
        for (int j = 0; j < 4; j++) Ts[ty*4+i][tx*4+j] = acc[i][j];

#pragma unroll
    for (int q = 0; q < 4; q++) {
        const int idx = tid + q*256;
        const int er = idx >> 4, f4 = idx & 15;
        *(float4*)&Wvs[er][f4*4] = *(const float4*)(Wv + (size_t)(h*64 + er) * Cdim + c0 + f4*4);
    }
    __syncthreads();

    float acc2[4][4];
#pragma unroll
    for (int i = 0; i < 4; i++)
#pragma unroll
        for (int j = 0; j < 4; j++) acc2[i][j] = 0.f;
    for (int j = 0; j < 64; j++) {
        float a4[4], b4[4];
#pragma unroll
        for (int i = 0; i < 4; i++) a4[i] = Ts[ty*4+i][j];
#pragma unroll
        for (int e = 0; e < 4; e++) b4[e] = Wvs[tx*4+e][j];
#pragma unroll
        for (int i = 0; i < 4; i++)
#pragma unroll
            for (int e = 0; e < 4; e++) acc2[i][e] += a4[i] * b4[e];
    }
    float* kvp = g_kvpart + (((size_t)ct * Bsz + b) * Hn + h) * (Dh * Dh);
#pragma unroll
    for (int i = 0; i < 4; i++)
#pragma unroll
        for (int e = 0; e < 4; e++)
            kvp[(size_t)(ty*4 + i) * 64 + tx*4 + e] = acc2[i][e];
}

// ---------------------------------------------------------------------------
// Kernel 4: W2 (fp32, proven)
// ---------------------------------------------------------------------------
__global__ __launch_bounds__(256) void w2_kernel(const float* __restrict__ Wo) {
    const int ot = blockIdx.x;
    const int h  = blockIdx.y;
    const int b  = blockIdx.z;

    __shared__ float Wos[64][68];
    __shared__ float kvs[64][68];

    const int tid = threadIdx.x;
    const int tx = tid & 15, ty = tid >> 4;

#pragma unroll
    for (int q = 0; q < 4; q++) {
        const int idx = tid + q*256;
        const int r = idx >> 4, f4 = idx & 15;
        *(float4*)&Wos[r][f4*4] = *(const float4*)(Wo + (size_t)(ot*64 + r) * Cdim + h*64 + f4*4);
    }
#pragma unroll
    for (int q = 0; q < 4; q++) {
        const int idx = tid + q*256;
        const int d = idx >> 4, f4 = idx & 15;
        float4 s = make_float4(0.f, 0.f, 0.f, 0.f);
        for (int t = 0; t < 8; t++) {
            const float4 v = *(const float4*)(g_kvpart +
                (((size_t)t * Bsz + b) * Hn + h) * 4096 + (size_t)d * 64 + f4*4);
            s.x += v.x; s.y += v.y; s.z += v.z; s.w += v.w;
        }
        *(float4*)&kvs[d][f4*4] = s;
    }
    __syncthreads();

    float acc[4][4];
#pragma unroll
    for (int i = 0; i < 4; i++)
#pragma unroll
        for (int j = 0; j < 4; j++) acc[i][j] = 0.f;
    for (int e = 0; e < 64; e++) {
        float a4[4], b4[4];
#pragma unroll
        for (int i = 0; i < 4; i++) a4[i] = Wos[ty*4+i][e];
#pragma unroll
        for (int j = 0; j < 4; j++) b4[j] = kvs[tx*4+j][e];
#pragma unroll
        for (int i = 0; i < 4; i++)
#pragma unroll
            for (int j = 0; j < 4; j++) acc[i][j] += a4[i] * b4[j];
    }
    float* W2 = g_W2 + (size_t)b * Cdim * Cdim;
    const float inv = 1.f / 64.f;
#pragma unroll
    for (int i = 0; i < 4; i++)
#pragma unroll
        for (int j = 0; j < 4; j++)
            W2[(size_t)(ot*64 + ty*4 + i) * Cdim + h*64 + tx*4 + j] = acc[i][j] * inv;
}

// ---------------------------------------------------------------------------
// Kernel 5: W3 (fp32, proven): W3[b] = W2[b] @ Wq
// ---------------------------------------------------------------------------
__global__ __launch_bounds__(256) void w3_kernel(const float* __restrict__ Wq) {
    const int nt = blockIdx.x;
    const int mt = blockIdx.y;
    const int b  = blockIdx.z;
    const float* A = g_W2 + (size_t)b * Cdim * Cdim;

    __shared__ float As_[16][68];
    __shared__ float Bs_[16][68];

    const int tid = threadIdx.x;
    const int tx = tid & 15, ty = tid >> 4;

    float acc[4][4];
#pragma unroll
    for (int i = 0; i < 4; i++)
#pragma unroll
        for (int j = 0; j < 4; j++) acc[i][j] = 0.f;

    for (int k = 0; k < 512; k += 16) {
        const int row = tid >> 2, c4 = tid & 3;
        float4 a4 = *(const float4*)(A + (size_t)(mt*64 + row) * Cdim + k + c4*4);
        const int kr = tid >> 4, f4 = tid & 15;
        float4 b4 = *(const float4*)(Wq + (size_t)(k + kr) * Cdim + nt*64 + f4*4);
        __syncthreads();
        As_[c4*4+0][row] = a4.x; As_[c4*4+1][row] = a4.y;
        As_[c4*4+2][row] = a4.z; As_[c4*4+3][row] = a4.w;
        *(float4*)&Bs_[kr][f4*4] = b4;
        __syncthreads();
#pragma unroll
        for (int kk = 0; kk < 16; kk++) {
            float a[4], bb[4];
            *(float4*)&a[0]  = *(const float4*)&As_[kk][ty*4];
            *(float4*)&bb[0] = *(const float4*)&Bs_[kk][tx*4];
#pragma unroll
            for (int i = 0; i < 4; i++)
#pragma unroll
                for (int j = 0; j < 4; j++) acc[i][j] += a[i] * bb[j];
        }
    }
    float* W3 = g_W3 + (size_t)b * Cdim * Cdim;
#pragma unroll
    for (int i = 0; i < 4; i++)
#pragma unroll
        for (int j = 0; j < 4; j++)
            W3[(size_t)(mt*64 + ty*4 + i) * Cdim + nt*64 + tx*4 + j] = acc[i][j];
}

// ---------------------------------------------------------------------------
// Kernel 6: out; f32x2 with PRE-DUPLICATED A in smem.
// out[b] = W3[b] @ Xl[b]  (M=512, N=8192, K=512)
// ---------------------------------------------------------------------------
__global__ __launch_bounds__(256, 2) void out_kernel(const float* __restrict__ Xl,
                                                     float* __restrict__ Out) {
    const int nt = blockIdx.x;
    const int mt = blockIdx.y;
    const int b  = blockIdx.z;
    const float* A  = g_W3 + (size_t)b * Cdim * Cdim;
    const float* Bm = Xl + (size_t)b * Cdim * Ldim;
    float* O        = Out + (size_t)b * Cdim * Ldim;

    __shared__ float Ad[16][272];   // [k][2m] duplicated A (+pad)
    __shared__ float Bs[16][132];   // [k][n]

    const int tid = threadIdx.x;
    const int tx = tid & 15, ty = tid >> 4;
    const int arow = tid >> 2, ac4 = tid & 3;
    const int kr0 = tid >> 5, c40 = tid & 31;
    const int n0 = nt * 128;

    unsigned long long acc[8][4];
#pragma unroll
    for (int i = 0; i < 8; i++)
#pragma unroll
        for (int j = 0; j < 4; j++) acc[i][j] = 0ull;

    const float* ApA = A + (size_t)(mt*128 + arow) * Cdim + ac4 * 4;
    const float* ApB = A + (size_t)(mt*128 + arow + 64) * Cdim + ac4 * 4;
    const float* BpA = Bm + (size_t)kr0 * Ldim + n0 + c40 * 4;
    const float* BpB = Bm + (size_t)(kr0 + 8) * Ldim + n0 + c40 * 4;

    float4 a0 = *(const float4*)(ApA);
    float4 a1 = *(const float4*)(ApB);
    float4 b0 = *(const float4*)(BpA);
    float4 b1 = *(const float4*)(BpB);

    for (int k = 0; k < 512; k += 16) {
        __syncthreads();
        *(unsigned long long*)&Ad[ac4*4+0][2*arow]       = dup2(a0.x);
        *(unsigned long long*)&Ad[ac4*4+1][2*arow]       = dup2(a0.y);
        *(unsigned long long*)&Ad[ac4*4+2][2*arow]       = dup2(a0.z);
        *(unsigned long long*)&Ad[ac4*4+3][2*arow]       = dup2(a0.w);
        *(unsigned long long*)&Ad[ac4*4+0][2*arow + 128] = dup2(a1.x);
        *(unsigned long long*)&Ad[ac4*4+1][2*arow + 128] = dup2(a1.y);
        *(unsigned long long*)&Ad[ac4*4+2][2*arow + 128] = dup2(a1.z);
        *(unsigned long long*)&Ad[ac4*4+3][2*arow + 128] = dup2(a1.w);
        *(float4*)&Bs[kr0][c40*4]     = b0;
        *(float4*)&Bs[kr0 + 8][c40*4] = b1;
        __syncthreads();
        if (k + 16 < 512) {
            a0 = *(const float4*)(ApA + k + 16);
            a1 = *(const float4*)(ApB + k + 16);
            b0 = *(const float4*)(BpA + (size_t)(k + 16) * Ldim);
            b1 = *(const float4*)(BpB + (size_t)(k + 16) * Ldim);
        }
#pragma unroll
        for (int kk = 0; kk < 16; kk++) {
            float4 aq0 = *(const float4*)&Ad[kk][8*ty];
            float4 aq1 = *(const float4*)&Ad[kk][8*ty + 4];
            float4 aq2 = *(const float4*)&Ad[kk][8*ty + 128];
            float4 aq3 = *(const float4*)&Ad[kk][8*ty + 132];
            unsigned long long ap[8];
            ap[0] = *(unsigned long long*)&aq0.x; ap[1] = *(unsigned long long*)&aq0.z;
            ap[2] = *(unsigned long long*)&aq1.x; ap[3] = *(unsigned long long*)&aq1.z;
            ap[4] = *(unsigned long long*)&aq2.x; ap[5] = *(unsigned long long*)&aq2.z;
            ap[6] = *(unsigned long long*)&aq3.x; ap[7] = *(unsigned long long*)&aq3.z;
            float4 bq0 = *(const float4*)&Bs[kk][tx*4];
            float4 bq1 = *(const float4*)&Bs[kk][64 + tx*4];
            unsigned long long bp[4];
            bp[0] = *(unsigned long long*)&bq0.x;
            bp[1] = *(unsigned long long*)&bq0.z;
            bp[2] = *(unsigned long long*)&bq1.x;
            bp[3] = *(unsigned long long*)&bq1.z;
#pragma unroll
            for (int i = 0; i < 8; i++)
#pragma unroll
                for (int j = 0; j < 4; j++) fma2(acc[i][j], ap[i], bp[j]);
        }
    }

#pragma unroll
    for (int i = 0; i < 8; i++) {
        const int m = mt*128 + ((i < 4) ? (ty*4 + 2*(i>>1) + (i&1)) : 0);
        // NOTE: with A-dup, ap[i] pairs are (m=ty*4+floor(i/2)*??) -- keep the
        // exact R11 mapping: ap index i corresponds to m offset below.
        (void)m;
    }
    // Epilogue: ap[i] held A value for m_i where
    //   i=0..3 -> m = ty*4 + i (both lanes of the pair are the SAME m; acc
    //   lanes differ in n, exactly as R11). i=4..7 -> m = 64 + ty*4 + (i-4).
#pragma unroll
    for (int i = 0; i < 8; i++) {
        const int m = mt*128 + ((i < 4) ? (ty*4 + i) : (64 + ty*4 + i - 4));
        float4 v0 = make_float4(lo32(acc[i][0]), hi32(acc[i][0]),
                                lo32(acc[i][1]), hi32(acc[i][1]));
        float4 v1 = make_float4(lo32(acc[i][2]), hi32(acc[i][2]),
                                lo32(acc[i][3]), hi32(acc[i][3]));
        *(float4*)(O + (size_t)m * Ldim + n0 + tx*4)      = v0;
        *(float4*)(O + (size_t)m * Ldim + n0 + 64 + tx*4) = v1;
    }
}

// ---------------------------------------------------------------------------
extern "C" void kernel_launch(void* const* d_in, const int* in_sizes, int n_in,
                              void* d_out, int out_size) {
    const float* x_local  = (const float*)d_in[0];
    const float* x_global = (const float*)d_in[1];
    const float* Wq       = (const float*)d_in[2];
    const float* Wk       = (const float*)d_in[3];
    const float* Wv       = (const float*)d_in[4];
    const float* Wo       = (const float*)d_in[5];
    float* out = (float*)d_out;

    gram_kernel<<<dim3(10, KSPLIT, 8), 256>>>(x_global);
    greduce_kernel<<<dim3(8192), 256>>>();
    kv_kernel<<<dim3(8, 8, 8), 256>>>(Wk, Wv);
    w2_kernel<<<dim3(8, 8, 8), 256>>>(Wo);
    w3_kernel<<<dim3(8, 8, 8), 256>>>(Wq);
    out_kernel<<<dim3(64, 4, 8), 256>>>(x_local, out);
}

// round 17
// speedup vs baseline: 2.0400x; 2.0400x over previous
#include <cuda_runtime.h>
#include <cstdint>

constexpr int Bsz  = 8;
constexpr int Cdim = 512;
constexpr int Ldim = 8192;
constexpr int Hn   = 8;
constexpr int Dh   = 64;
constexpr int KSPLIT = 8;   // gram split-K slabs

// ---------------- scratch (static device arrays; never passed as kernel args) --
__device__ float g_Gpart[(size_t)KSPLIT * Bsz * Cdim * Cdim];   // 64 MB
__device__ float g_G[(size_t)Bsz * Cdim * Cdim];
__device__ float g_kvpart[8ull * Bsz * Hn * Dh * Dh];
__device__ float g_W2[(size_t)Bsz * Cdim * Cdim];
__device__ float g_W3[(size_t)Bsz * Cdim * Cdim];

// packed dual-FMA helpers (base PTX, sm_100+)
static __device__ __forceinline__ unsigned long long dup2(float a) {
    unsigned long long r;
    asm("mov.b64 %0, {%1, %1};" : "=l"(r) : "f"(a));
    return r;
}
static __device__ __forceinline__ void fma2(unsigned long long& c,
                                            unsigned long long a,
                                            unsigned long long b) {
    asm("fma.rn.f32x2 %0, %1, %2, %0;" : "+l"(c) : "l"(a), "l"(b));
}
static __device__ __forceinline__ float lo32(unsigned long long v) {
    return __uint_as_float((unsigned)(v & 0xFFFFFFFFull));
}
static __device__ __forceinline__ float hi32(unsigned long long v) {
    return __uint_as_float((unsigned)(v >> 32));
}

// ---------------------------------------------------------------------------
// Kernel 1: Gram partials; f32x2 + register-prefetch (R15-proven, FROZEN).
// G[b] = Xg[b] @ Xg[b]^T, 10 symmetric 128x128 tile pairs, split-K=8 slabs.
// ---------------------------------------------------------------------------
__global__ __launch_bounds__(256, 2) void gram_kernel(const float* __restrict__ Xg) {
    const int pair = blockIdx.x, ks = blockIdx.y, b = blockIdx.z;
    int ti = 0, t = pair;
    while (t >= 4 - ti) { t -= 4 - ti; ti++; }
    const int tj = ti + t;

    const float* X   = Xg + (size_t)b * Cdim * Ldim;
    const float* Ag0 = X + (size_t)ti * 128 * Ldim;
    const float* Bg0 = X + (size_t)tj * 128 * Ldim;
    const int k0 = ks * 1024;

    __shared__ float As[16][132];
    __shared__ float Bs[16][132];

    const int tid = threadIdx.x;
    const int tx = tid & 15, ty = tid >> 4;
    const int lrow = tid >> 2, lc4 = tid & 3;

    unsigned long long acc[8][4];
#pragma unroll
    for (int i = 0; i < 8; i++)
#pragma unroll
        for (int j = 0; j < 4; j++) acc[i][j] = 0ull;

    const float* ApA = Ag0 + (size_t)lrow * Ldim + lc4 * 4 + k0;
    const float* ApB = Ag0 + (size_t)(lrow + 64) * Ldim + lc4 * 4 + k0;
    const float* BpA = Bg0 + (size_t)lrow * Ldim + lc4 * 4 + k0;
    const float* BpB = Bg0 + (size_t)(lrow + 64) * Ldim + lc4 * 4 + k0;

    float4 a0 = *(const float4*)(ApA);
    float4 a1 = *(const float4*)(ApB);
    float4 b0 = *(const float4*)(BpA);
    float4 b1 = *(const float4*)(BpB);

    for (int kt = 0; kt < 1024; kt += 16) {
        __syncthreads();
        As[lc4*4+0][lrow]    = a0.x; As[lc4*4+1][lrow]    = a0.y;
        As[lc4*4+2][lrow]    = a0.z; As[lc4*4+3][lrow]    = a0.w;
        As[lc4*4+0][lrow+64] = a1.x; As[lc4*4+1][lrow+64] = a1.y;
        As[lc4*4+2][lrow+64] = a1.z; As[lc4*4+3][lrow+64] = a1.w;
        Bs[lc4*4+0][lrow]    = b0.x; Bs[lc4*4+1][lrow]    = b0.y;
        Bs[lc4*4+2][lrow]    = b0.z; Bs[lc4*4+3][lrow]    = b0.w;
        Bs[lc4*4+0][lrow+64] = b1.x; Bs[lc4*4+1][lrow+64] = b1.y;
        Bs[lc4*4+2][lrow+64] = b1.z; Bs[lc4*4+3][lrow+64] = b1.w;
        __syncthreads();
        if (kt + 16 < 1024) {
            a0 = *(const float4*)(ApA + kt + 16);
            a1 = *(const float4*)(ApB + kt + 16);
            b0 = *(const float4*)(BpA + kt + 16);
            b1 = *(const float4*)(BpB + kt + 16);
        }
#pragma unroll
        for (int kk = 0; kk < 16; kk++) {
            float af[8];
            *(float4*)&af[0] = *(const float4*)&As[kk][ty*4];
            *(float4*)&af[4] = *(const float4*)&As[kk][64 + ty*4];
            float4 bq0 = *(const float4*)&Bs[kk][tx*4];
            float4 bq1 = *(const float4*)&Bs[kk][64 + tx*4];
            unsigned long long bp[4];
            bp[0] = *(unsigned long long*)&bq0.x;
            bp[1] = *(unsigned long long*)&bq0.z;
            bp[2] = *(unsigned long long*)&bq1.x;
            bp[3] = *(unsigned long long*)&bq1.z;
#pragma unroll
            for (int i = 0; i < 8; i++) {
                const unsigned long long aa = dup2(af[i]);
#pragma unroll
                for (int j = 0; j < 4; j++) fma2(acc[i][j], aa, bp[j]);
            }
        }
    }

    float* Gp = g_Gpart + ((size_t)ks * Bsz + b) * Cdim * Cdim;
#pragma unroll
    for (int i = 0; i < 8; i++) {
        const int m = ti * 128 + ((i < 4) ? (ty*4 + i) : (64 + ty*4 + i - 4));
        float av[8];
#pragma unroll
        for (int j = 0; j < 4; j++) { av[2*j] = lo32(acc[i][j]); av[2*j+1] = hi32(acc[i][j]); }
#pragma unroll
        for (int j = 0; j < 8; j++) {
            const int n = tj * 128 + ((j < 4) ? (tx*4 + j) : (64 + tx*4 + j - 4));
            Gp[(size_t)m * Cdim + n] = av[j];
            if (ti != tj) Gp[(size_t)n * Cdim + m] = av[j];
        }
    }
}

// Kernel 2: reduce the 8 split-K slabs (deterministic).
__global__ void greduce_kernel() {
    const size_t n   = (size_t)Bsz * Cdim * Cdim;
    const size_t idx = (size_t)blockIdx.x * blockDim.x + threadIdx.x;
    if (idx < n) {
        float s = 0.f;
#pragma unroll
        for (int t = 0; t < KSPLIT; t++) s += g_Gpart[(size_t)t * n + idx];
        g_G[idx] = s;
    }
}

// ---------------------------------------------------------------------------
// Kernel 3: kv partials; phase-1 in f32x2 (m-pair packing; R13-verified).
// kv[b,h] = Wk_h @ G[b] @ Wv_h^T
// ---------------------------------------------------------------------------
__global__ __launch_bounds__(256) void kv_kernel(const float* __restrict__ Wk,
                                                 const float* __restrict__ Wv) {
    const int ct = blockIdx.x;
    const int h  = blockIdx.y;
    const int b  = blockIdx.z;
    const float* G = g_G + (size_t)b * Cdim * Cdim;
    const int c0 = ct * 64;

    __shared__ float Wks[16][68];
    __shared__ float Gs[16][68];
    __shared__ float Ts[64][68];
    __shared__ float Wvs[64][68];

    const int tid = threadIdx.x;
    const int tx = tid & 15, ty = tid >> 4;

    unsigned long long accp[2][4];
#pragma unroll
    for (int p = 0; p < 2; p++)
#pragma unroll
        for (int j = 0; j < 4; j++) accp[p][j] = 0ull;

    for (int k = 0; k < 512; k += 16) {
        const int row = tid >> 2, c4 = tid & 3;
        float4 w4 = *(const float4*)(Wk + (size_t)(h*64 + row) * Cdim + k + c4*4);
        const int kr = tid >> 4, f4 = tid & 15;
        float4 g4 = *(const float4*)(G + (size_t)(k + kr) * Cdim + c0 + f4*4);
        __syncthreads();
        Wks[c4*4+0][row] = w4.x; Wks[c4*4+1][row] = w4.y;
        Wks[c4*4+2][row] = w4.z; Wks[c4*4+3][row] = w4.w;
        *(float4*)&Gs[kr][f4*4] = g4;
        __syncthreads();
#pragma unroll
        for (int kk = 0; kk < 16; kk++) {
            float4 aq = *(const float4*)&Wks[kk][ty*4];
            unsigned long long ap0 = *(unsigned long long*)&aq.x;
            unsigned long long ap1 = *(unsigned long long*)&aq.z;
            float4 gq = *(const float4*)&Gs[kk][tx*4];
            unsigned long long bd[4] = { dup2(gq.x), dup2(gq.y), dup2(gq.z), dup2(gq.w) };
#pragma unroll
            for (int j = 0; j < 4; j++) { fma2(accp[0][j], ap0, bd[j]); fma2(accp[1][j], ap1, bd[j]); }
        }
    }
#pragma unroll
    for (int p = 0; p < 2; p++)
#pragma unroll
        for (int j = 0; j < 4; j++) {
            Ts[ty*4 + 2*p][tx*4 + j]     = lo32(accp[p][j]);
            Ts[ty*4 + 2*p + 1][tx*4 + j] = hi32(accp[p][j]);
        }

#pragma unroll
    for (int q = 0; q < 4; q++) {
        const int idx = tid + q*256;
        const int er = idx >> 4, f4 = idx & 15;
        *(float4*)&Wvs[er][f4*4] = *(const float4*)(Wv + (size_t)(h*64 + er) * Cdim + c0 + f4*4);
    }
    __syncthreads();

    float acc2[4][4];
#pragma unroll
    for (int i = 0; i < 4; i++)
#pragma unroll
        for (int j = 0; j < 4; j++) acc2[i][j] = 0.f;
    for (int j = 0; j < 64; j++) {
        float a4[4], b4[4];
#pragma unroll
        for (int i = 0; i < 4; i++) a4[i] = Ts[ty*4+i][j];
#pragma unroll
        for (int e = 0; e < 4; e++) b4[e] = Wvs[tx*4+e][j];
#pragma unroll
        for (int i = 0; i < 4; i++)
#pragma unroll
            for (int e = 0; e < 4; e++) acc2[i][e] += a4[i] * b4[e];
    }
    float* kvp = g_kvpart + (((size_t)ct * Bsz + b) * Hn + h) * (Dh * Dh);
#pragma unroll
    for (int i = 0; i < 4; i++)
#pragma unroll
        for (int e = 0; e < 4; e++)
            kvp[(size_t)(ty*4 + i) * 64 + tx*4 + e] = acc2[i][e];
}

// ---------------------------------------------------------------------------
// Kernel 4: W2 (fp32, proven)
// ---------------------------------------------------------------------------
__global__ __launch_bounds__(256) void w2_kernel(const float* __restrict__ Wo) {
    const int ot = blockIdx.x;
    const int h  = blockIdx.y;
    const int b  = blockIdx.z;

    __shared__ float Wos[64][68];
    __shared__ float kvs[64][68];

    const int tid = threadIdx.x;
    const int tx = tid & 15, ty = tid >> 4;

#pragma unroll
    for (int q = 0; q < 4; q++) {
        const int idx = tid + q*256;
        const int r = idx >> 4, f4 = idx & 15;
        *(float4*)&Wos[r][f4*4] = *(const float4*)(Wo + (size_t)(ot*64 + r) * Cdim + h*64 + f4*4);
    }
#pragma unroll
    for (int q = 0; q < 4; q++) {
        const int idx = tid + q*256;
        const int d = idx >> 4, f4 = idx & 15;
        float4 s = make_float4(0.f, 0.f, 0.f, 0.f);
        for (int t = 0; t < 8; t++) {
            const float4 v = *(const float4*)(g_kvpart +
                (((size_t)t * Bsz + b) * Hn + h) * 4096 + (size_t)d * 64 + f4*4);
            s.x += v.x; s.y += v.y; s.z += v.z; s.w += v.w;
        }
        *(float4*)&kvs[d][f4*4] = s;
    }
    __syncthreads();

    float acc[4][4];
#pragma unroll
    for (int i = 0; i < 4; i++)
#pragma unroll
        for (int j = 0; j < 4; j++) acc[i][j] = 0.f;
    for (int e = 0; e < 64; e++) {
        float a4[4], b4[4];
#pragma unroll
        for (int i = 0; i < 4; i++) a4[i] = Wos[ty*4+i][e];
#pragma unroll
        for (int j = 0; j < 4; j++) b4[j] = kvs[tx*4+j][e];
#pragma unroll
        for (int i = 0; i < 4; i++)
#pragma unroll
            for (int j = 0; j < 4; j++) acc[i][j] += a4[i] * b4[j];
    }
    float* W2 = g_W2 + (size_t)b * Cdim * Cdim;
    const float inv = 1.f / 64.f;
#pragma unroll
    for (int i = 0; i < 4; i++)
#pragma unroll
        for (int j = 0; j < 4; j++)
            W2[(size_t)(ot*64 + ty*4 + i) * Cdim + h*64 + tx*4 + j] = acc[i][j] * inv;
}

// ---------------------------------------------------------------------------
// Kernel 5: W3 in f32x2 (m-pair packing; R13-verified): W3[b] = W2[b] @ Wq
// ---------------------------------------------------------------------------
__global__ __launch_bounds__(256) void w3_kernel(const float* __restrict__ Wq) {
    const int nt = blockIdx.x;
    const int mt = blockIdx.y;
    const int b  = blockIdx.z;
    const float* A = g_W2 + (size_t)b * Cdim * Cdim;

    __shared__ float As_[16][68];
    __shared__ float Bs_[16][68];

    const int tid = threadIdx.x;
    const int tx = tid & 15, ty = tid >> 4;

    unsigned long long accp[2][4];
#pragma unroll
    for (int p = 0; p < 2; p++)
#pragma unroll
        for (int j = 0; j < 4; j++) accp[p][j] = 0ull;

    for (int k = 0; k < 512; k += 16) {
        const int row = tid >> 2, c4 = tid & 3;
        float4 a4 = *(const float4*)(A + (size_t)(mt*64 + row) * Cdim + k + c4*4);
        const int kr = tid >> 4, f4 = tid & 15;
        float4 b4 = *(const float4*)(Wq + (size_t)(k + kr) * Cdim + nt*64 + f4*4);
        __syncthreads();
        As_[c4*4+0][row] = a4.x; As_[c4*4+1][row] = a4.y;
        As_[c4*4+2][row] = a4.z; As_[c4*4+3][row] = a4.w;
        *(float4*)&Bs_[kr][f4*4] = b4;
        __syncthreads();
#pragma unroll
        for (int kk = 0; kk < 16; kk++) {
            float4 aq = *(const float4*)&As_[kk][ty*4];
            unsigned long long ap0 = *(unsigned long long*)&aq.x;
            unsigned long long ap1 = *(unsigned long long*)&aq.z;
            float4 bq = *(const float4*)&Bs_[kk][tx*4];
            unsigned long long bd[4] = { dup2(bq.x), dup2(bq.y), dup2(bq.z), dup2(bq.w) };
#pragma unroll
            for (int j = 0; j < 4; j++) { fma2(accp[0][j], ap0, bd[j]); fma2(accp[1][j], ap1, bd[j]); }
        }
    }
    float* W3 = g_W3 + (size_t)b * Cdim * Cdim;
#pragma unroll
    for (int p = 0; p < 2; p++)
#pragma unroll
        for (int j = 0; j < 4; j++) {
            W3[(size_t)(mt*64 + ty*4 + 2*p) * Cdim + nt*64 + tx*4 + j]     = lo32(accp[p][j]);
            W3[(size_t)(mt*64 + ty*4 + 2*p + 1) * Cdim + nt*64 + tx*4 + j] = hi32(accp[p][j]);
        }
}

// ---------------------------------------------------------------------------
// Kernel 6: out; f32x2 + register-prefetch (R15-proven, FROZEN).
// out[b] = W3[b] @ Xl[b]  (M=512, N=8192, K=512)
// ---------------------------------------------------------------------------
__global__ __launch_bounds__(256, 2) void out_kernel(const float* __restrict__ Xl,
                                                     float* __restrict__ Out) {
    const int nt = blockIdx.x;
    const int mt = blockIdx.y;
    const int b  = blockIdx.z;
    const float* A  = g_W3 + (size_t)b * Cdim * Cdim;
    const float* Bm = Xl + (size_t)b * Cdim * Ldim;
    float* O        = Out + (size_t)b * Cdim * Ldim;

    __shared__ float As[16][132];
    __shared__ float Bs[16][132];

    const int tid = threadIdx.x;
    const int tx = tid & 15, ty = tid >> 4;
    const int arow = tid >> 2, ac4 = tid & 3;
    const int kr0 = tid >> 5, c40 = tid & 31;
    const int n0 = nt * 128;

    unsigned long long acc[8][4];
#pragma unroll
    for (int i = 0; i < 8; i++)
#pragma unroll
        for (int j = 0; j < 4; j++) acc[i][j] = 0ull;

    const float* ApA = A + (size_t)(mt*128 + arow) * Cdim + ac4 * 4;
    const float* ApB = A + (size_t)(mt*128 + arow + 64) * Cdim + ac4 * 4;
    const float* BpA = Bm + (size_t)kr0 * Ldim + n0 + c40 * 4;
    const float* BpB = Bm + (size_t)(kr0 + 8) * Ldim + n0 + c40 * 4;

    float4 a0 = *(const float4*)(ApA);
    float4 a1 = *(const float4*)(ApB);
    float4 b0 = *(const float4*)(BpA);
    float4 b1 = *(const float4*)(BpB);

    for (int k = 0; k < 512; k += 16) {
        __syncthreads();
        As[ac4*4+0][arow]    = a0.x; As[ac4*4+1][arow]    = a0.y;
        As[ac4*4+2][arow]    = a0.z; As[ac4*4+3][arow]    = a0.w;
        As[ac4*4+0][arow+64] = a1.x; As[ac4*4+1][arow+64] = a1.y;
        As[ac4*4+2][arow+64] = a1.z; As[ac4*4+3][arow+64] = a1.w;
        *(float4*)&Bs[kr0][c40*4]     = b0;
        *(float4*)&Bs[kr0 + 8][c40*4] = b1;
        __syncthreads();
        if (k + 16 < 512) {
            a0 = *(const float4*)(ApA + k + 16);
            a1 = *(const float4*)(ApB + k + 16);
            b0 = *(const float4*)(BpA + (size_t)(k + 16) * Ldim);
            b1 = *(const float4*)(BpB + (size_t)(k + 16) * Ldim);
        }
#pragma unroll
        for (int kk = 0; kk < 16; kk++) {
            float af[8];
            *(float4*)&af[0] = *(const float4*)&As[kk][ty*4];
            *(float4*)&af[4] = *(const float4*)&As[kk][64 + ty*4];
            float4 bq0 = *(const float4*)&Bs[kk][tx*4];
            float4 bq1 = *(const float4*)&Bs[kk][64 + tx*4];
            unsigned long long bp[4];
            bp[0] = *(unsigned long long*)&bq0.x;
            bp[1] = *(unsigned long long*)&bq0.z;
            bp[2] = *(unsigned long long*)&bq1.x;
            bp[3] = *(unsigned long long*)&bq1.z;
#pragma unroll
            for (int i = 0; i < 8; i++) {
                const unsigned long long aa = dup2(af[i]);
#pragma unroll
                for (int j = 0; j < 4; j++) fma2(acc[i][j], aa, bp[j]);
            }
        }
    }

#pragma unroll
    for (int i = 0; i < 8; i++) {
        const int m = mt*128 + ((i < 4) ? (ty*4 + i) : (64 + ty*4 + i - 4));
        float4 v0 = make_float4(lo32(acc[i][0]), hi32(acc[i][0]),
                                lo32(acc[i][1]), hi32(acc[i][1]));
        float4 v1 = make_float4(lo32(acc[i][2]), hi32(acc[i][2]),
                                lo32(acc[i][3]), hi32(acc[i][3]));
        *(float4*)(O + (size_t)m * Ldim + n0 + tx*4)      = v0;
        *(float4*)(O + (size_t)m * Ldim + n0 + 64 + tx*4) = v1;
    }
}

// ---------------------------------------------------------------------------
extern "C" void kernel_launch(void* const* d_in, const int* in_sizes, int n_in,
                              void* d_out, int out_size) {
    const float* x_local  = (const float*)d_in[0];
    const float* x_global = (const float*)d_in[1];
    const float* Wq       = (const float*)d_in[2];
    const float* Wk       = (const float*)d_in[3];
    const float* Wv       = (const float*)d_in[4];
    const float* Wo       = (const float*)d_in[5];
    float* out = (float*)d_out;

    gram_kernel<<<dim3(10, KSPLIT, 8), 256>>>(x_global);
    greduce_kernel<<<dim3(8192), 256>>>();
    kv_kernel<<<dim3(8, 8, 8), 256>>>(Wk, Wv);
    w2_kernel<<<dim3(8, 8, 8), 256>>>(Wo);
    w3_kernel<<<dim3(8, 8, 8), 256>>>(Wq);
    out_kernel<<<dim3(64, 4, 8), 256>>>(x_local, out);
}